// round 10
// baseline (speedup 1.0000x reference)
#include <cuda_runtime.h>
#include <cuda_bf16.h>
#include <stdint.h>

// ---------------------------------------------------------------------------
// Problem constants
// ---------------------------------------------------------------------------
#define BATCH     16
#define N_PROP    2000
#define N_PAD     2048
#define MAX_GT    100
#define IMG_H     160
#define IMG_W     160
#define T_ROIS    200
#define NUM_POS   66
#define NUM_NEG   134
#define MH        28
#define MW        28

// output layout (float32, tuple order: rois, class_ids, deltas, masks)
#define OFF_ROIS  0
#define OFF_CLS   (BATCH * T_ROIS * 4)                 // 12800
#define OFF_DEL   (OFF_CLS + BATCH * T_ROIS)           // 16000
#define OFF_MASK  (OFF_DEL + BATCH * T_ROIS * 4)       // 28800

// XLA rewrites x / const -> x * (1/const); replicate for bit-exactness.
#define RECIP_033  (1.0f / 0.33f)
#define RECIP_27   (1.0f / 27.0f)

// ---------------------------------------------------------------------------
// Scratch (__device__ globals; no allocations allowed)
// ---------------------------------------------------------------------------
__device__ unsigned long long g_ptop[BATCH][NUM_POS];
__device__ unsigned long long g_ntop[BATCH][NUM_NEG];
__device__ int   g_pg[BATCH][NUM_POS];
__device__ int   g_P[BATCH];
__device__ float g_mbox[BATCH * NUM_POS * 4];
__device__ int   g_mg[BATCH * NUM_POS];
__device__ int   g_mv[BATCH * NUM_POS];

// ---------------------------------------------------------------------------
// JAX threefry2x32 (partitionable mode semantics)
// ---------------------------------------------------------------------------
__host__ __device__ __forceinline__ void tf2x32(unsigned k0, unsigned k1,
                                                unsigned x0, unsigned x1,
                                                unsigned &o0, unsigned &o1) {
    unsigned ks0 = k0, ks1 = k1, ks2 = k0 ^ k1 ^ 0x1BD11BDAu;
    x0 += ks0; x1 += ks1;
#define TFR(r) { x0 += x1; x1 = (x1 << (r)) | (x1 >> (32 - (r))); x1 ^= x0; }
    TFR(13) TFR(15) TFR(26) TFR(6)  x0 += ks1; x1 += ks2 + 1u;
    TFR(17) TFR(29) TFR(16) TFR(24) x0 += ks2; x1 += ks0 + 2u;
    TFR(13) TFR(15) TFR(26) TFR(6)  x0 += ks0; x1 += ks1 + 3u;
    TFR(17) TFR(29) TFR(16) TFR(24) x0 += ks1; x1 += ks2 + 4u;
    TFR(13) TFR(15) TFR(26) TFR(6)  x0 += ks2; x1 += ks0 + 5u;
#undef TFR
    o0 = x0; o1 = x1;
}

__device__ __forceinline__ float u01_from_bits(unsigned bits) {
    return __uint_as_float((bits >> 9) | 0x3f800000u) - 1.0f;
}

// order-preserving float->u32 + ~idx tiebreak (stable top_k when sorted desc)
__device__ __forceinline__ unsigned long long pack_key(float f, int idx) {
    unsigned u = __float_as_uint(f);
    u = (u & 0x80000000u) ? ~u : (u | 0x80000000u);
    return (((unsigned long long)u) << 32) | (unsigned)(~idx);
}

struct KeySet {
    unsigned kp0[BATCH], kp1[BATCH], kn0[BATCH], kn1[BATCH];
};

#define NAMED_BAR_256() asm volatile("bar.sync 1, 256;" ::: "memory")

// full 2048 bitonic (descending) — exact fallback path only
__device__ __forceinline__ void bitonic_desc_2048(unsigned long long* s, int tid) {
    for (unsigned k = 2; k <= N_PAD; k <<= 1) {
        for (unsigned j = k >> 1; j > 0; j >>= 1) {
            __syncthreads();
            for (unsigned i = tid; i < N_PAD; i += 1024) {
                const unsigned ixj = i ^ j;
                if (ixj > i) {
                    const unsigned long long a = s[i], c = s[ixj];
                    const bool swp = ((i & k) == 0) ? (a < c) : (a > c);
                    if (swp) { s[i] = c; s[ixj] = a; }
                }
            }
        }
    }
    __syncthreads();
}

// ---------------------------------------------------------------------------
// Kernel 1 (fused): 32 blocks = (image, list).
//  * compute this list's keys (division-free exact IoU>=0.5 classification)
//  * exact top-K via bucket histogram + candidate compaction + 256-sort
//  * pos block: P, per-positive argmax (rounded divides reproduced here only),
//    mask metadata
// ---------------------------------------------------------------------------
__global__ void __launch_bounds__(1024)
k_select(const float4* __restrict__ proposals,
         const int*    __restrict__ gt_cls,
         const float4* __restrict__ gt_boxes,
         KeySet keys) {
    const int b    = blockIdx.x >> 1;
    const int list = blockIdx.x & 1;
    const int K    = list ? NUM_NEG : NUM_POS;
    const int tid  = threadIdx.x;

    __shared__ float4 sg[MAX_GT];
    __shared__ float  sa[MAX_GT];
    __shared__ int    sv[MAX_GT];
    __shared__ unsigned long long s_keys[N_PAD];
    __shared__ unsigned s_hA[N_PAD];
    __shared__ unsigned s_hB[N_PAD];
    __shared__ unsigned long long s_cand[256];
    __shared__ unsigned s_cnt, s_T;

    for (int i = tid; i < MAX_GT; i += 1024) {
        const float4 q = gt_boxes[b * MAX_GT + i];
        sg[i] = q;
        sa[i] = __fmul_rn(__fsub_rn(q.z, q.x), __fsub_rn(q.w, q.y));
        sv[i] = gt_cls[b * MAX_GT + i] > 0;
    }
    for (int i = tid; i < N_PAD; i += 1024) s_hA[i] = 0u;
    if (tid == 0) s_cnt = 0u;
    __syncthreads();

    const unsigned rk0 = list ? keys.kn0[b] : keys.kp0[b];
    const unsigned rk1 = list ? keys.kn1[b] : keys.kp1[b];

    // ---- keys + histogram (bucket = top 11 bits of 64-bit key) ----
    for (int i = tid; i < N_PAD; i += 1024) {
        unsigned long long key = 0ull;
        if (i < N_PROP) {
            const float4 p = proposals[b * N_PROP + i];
            const bool vp = (p.x != 0.f) || (p.y != 0.f) ||
                            (p.z != 0.f) || (p.w != 0.f);
            const float a1 = __fmul_rn(__fsub_rn(p.z, p.x), __fsub_rn(p.w, p.y));
            bool pos = false;
            // fl(inter/u) >= 0.5 <=> 2*inter >= u || (u - 2*inter) <= u*2^-25
            // (power-of-2 scalings exact; Sterbenz in the deciding band)
            #pragma unroll 4
            for (int g = 0; g < MAX_GT; ++g) {
                if (!sv[g]) continue;
                const float4 q = sg[g];
                const float ih = fmaxf(__fsub_rn(fminf(p.z, q.z), fmaxf(p.x, q.x)), 0.f);
                const float iw = fmaxf(__fsub_rn(fminf(p.w, q.w), fmaxf(p.y, q.y)), 0.f);
                const float inter = __fmul_rn(ih, iw);
                const float u = fmaxf(__fsub_rn(__fadd_rn(a1, sa[g]), inter), 1e-10f);
                const float t2 = __fmul_rn(2.0f, inter);
                pos |= (t2 >= u) ||
                       (__fsub_rn(u, t2) <= __fmul_rn(u, 0x1p-25f));
            }
            const bool want = list ? (!pos && vp) : (pos && vp);
            unsigned o0, o1;
            tf2x32(rk0, rk1, 0u, (unsigned)i, o0, o1);
            key = pack_key(want ? u01_from_bits(o0 ^ o1) : -1.0f, i);
        }
        s_keys[i] = key;
        atomicAdd(&s_hA[(unsigned)(key >> 53)], 1u);
    }
    __syncthreads();

    // ---- suffix counts: reverse + Hillis-Steele inclusive scan ----
    for (int i = tid; i < N_PAD; i += 1024) s_hB[i] = s_hA[2047 - i];
    __syncthreads();
    unsigned *src = s_hB, *dst = s_hA;
    for (int off = 1; off < N_PAD; off <<= 1) {
        for (int i = tid; i < N_PAD; i += 1024)
            dst[i] = src[i] + ((i >= off) ? src[i - off] : 0u);
        __syncthreads();
        unsigned* t = src; src = dst; dst = t;
    }
    // suffix(bkt) = src[2047 - bkt]

    // ---- threshold bucket T: suffix(T) >= K, suffix(T+1) < K (unique) ----
    for (int i = tid; i < N_PAD; i += 1024) {
        const unsigned Sb  = src[2047 - i];
        const unsigned Sb1 = (i == 2047) ? 0u : src[2046 - i];
        if (Sb >= (unsigned)K && Sb1 < (unsigned)K) s_T = (unsigned)i;
    }
    __syncthreads();
    const unsigned T = s_T;

    // ---- compact candidates (buckets >= T) ----
    for (int i = tid; i < N_PAD; i += 1024) {
        const unsigned long long key = s_keys[i];
        if ((unsigned)(key >> 53) >= T) {
            const unsigned p = atomicAdd(&s_cnt, 1u);
            if (p < 256u) s_cand[p] = key;
        }
    }
    __syncthreads();
    const unsigned cnt = s_cnt;

    const unsigned long long* res;
    if (cnt > 256u) {
        // exact fallback (valid < K, or pathological bucket collisions)
        bitonic_desc_2048(s_keys, tid);
        res = s_keys;
    } else {
        if (tid < 256 && (unsigned)tid >= cnt) s_cand[tid] = 0ull;
        __syncthreads();
        // hybrid bitonic-256 descending: j<=16 via shfl, j>=32 via smem+named bar
        if (tid < 256) {
            unsigned long long e = s_cand[tid];
            for (unsigned k = 2; k <= 256; k <<= 1) {
                for (unsigned j = k >> 1; j > 0; j >>= 1) {
                    const bool keepMax =
                        (((tid & k) == 0u) == ((tid & j) == 0u));
                    if (j <= 16) {
                        const unsigned long long p =
                            __shfl_xor_sync(0xFFFFFFFFu, e, j);
                        e = keepMax ? (e > p ? e : p) : (e < p ? e : p);
                    } else {
                        s_cand[tid] = e;
                        NAMED_BAR_256();
                        const unsigned long long p = s_cand[tid ^ j];
                        e = keepMax ? (e > p ? e : p) : (e < p ? e : p);
                        NAMED_BAR_256();
                    }
                }
            }
            s_cand[tid] = e;
        }
        __syncthreads();
        res = s_cand;
    }

    // ---- emit selection results ----
    if (list) {
        if (tid < NUM_NEG) g_ntop[b][tid] = res[tid];
        return;
    }

    if (tid < NUM_POS) {
        const unsigned long long key = res[tid];
        const int n = (int)(~(unsigned)key);
        const int v = ((unsigned)(key >> 32)) > 0x80000000u;
        g_ptop[b][tid] = key;
        const float4 p = proposals[b * N_PROP + n];
        const int mi = b * NUM_POS + tid;
        g_mbox[mi * 4 + 0] = p.x; g_mbox[mi * 4 + 1] = p.y;
        g_mbox[mi * 4 + 2] = p.z; g_mbox[mi * 4 + 3] = p.w;
        g_mv[mi] = v;
    }
    if (tid == 0) {
        int P = 0;
        for (int i = 0; i < NUM_POS; ++i)
            P += (((unsigned)(res[i] >> 32)) > 0x80000000u);
        g_P[b] = P;
    }

    // warp-per-positive argmax over where(valid, fl(inter/union), -1)
    const int wid = tid >> 5, lane = tid & 31;
    for (int slot = wid; slot < NUM_POS; slot += 32) {
        const int n = (int)(~(unsigned)res[slot]);
        const float4 p = proposals[b * N_PROP + n];
        const float a1 = __fmul_rn(__fsub_rn(p.z, p.x), __fsub_rn(p.w, p.y));

        float bestv = -2.0f; int bestg = 0;
        #pragma unroll 4
        for (int k = 0; k < 4; ++k) {
            const int g = lane + k * 32;
            if (g < MAX_GT) {
                float v = -1.0f;
                if (sv[g]) {
                    const float4 q = sg[g];
                    const float ih = fmaxf(__fsub_rn(fminf(p.z, q.z), fmaxf(p.x, q.x)), 0.f);
                    const float iw = fmaxf(__fsub_rn(fminf(p.w, q.w), fmaxf(p.y, q.y)), 0.f);
                    const float inter = __fmul_rn(ih, iw);
                    const float u = fmaxf(__fsub_rn(__fadd_rn(a1, sa[g]), inter), 1e-10f);
                    v = __fdiv_rn(inter, u);
                }
                if (v > bestv) { bestv = v; bestg = g; }   // ascending g: first-max
            }
        }
        #pragma unroll
        for (int off = 16; off; off >>= 1) {
            const float ov = __shfl_down_sync(0xFFFFFFFFu, bestv, off);
            const int   og = __shfl_down_sync(0xFFFFFFFFu, bestg, off);
            if (ov > bestv || (ov == bestv && og < bestg)) { bestv = ov; bestg = og; }
        }
        if (lane == 0) {
            g_pg[b][slot] = bestg;
            g_mg[b * NUM_POS + slot] = bestg;
        }
    }
}

// ---------------------------------------------------------------------------
// Kernel 2: mask crop_and_resize (tf bilinear) — 256 threads, pixel loop
// ---------------------------------------------------------------------------
__global__ void __launch_bounds__(256)
k_mask(const float* __restrict__ masks_in,
       float* __restrict__ out) {
    const int slot = blockIdx.x;
    const int b    = blockIdx.y;
    float* dst = out + OFF_MASK + (size_t)(b * T_ROIS + slot) * (MH * MW);
    const int tid = threadIdx.x;

    int v = 0, g = 0;
    float y1 = 0.f, x1 = 0.f, y2 = 0.f, x2 = 0.f;
    if (slot < NUM_POS) {
        const int mi = b * NUM_POS + slot;
        v = g_mv[mi];
        g = g_mg[mi];
        y1 = g_mbox[mi * 4 + 0]; x1 = g_mbox[mi * 4 + 1];
        y2 = g_mbox[mi * 4 + 2]; x2 = g_mbox[mi * 4 + 3];
    }
    if (!v) {
        for (int i = tid; i < MH * MW; i += 256) dst[i] = 0.0f;
        return;
    }

    const size_t base = (size_t)b * IMG_H * IMG_W * MAX_GT + g;
    const float dy = __fsub_rn(y2, y1);
    const float dx = __fsub_rn(x2, x1);

    for (int i = tid; i < MH * MW; i += 256) {
        const int r = i / MW, c = i % MW;
        const float ty = __fmul_rn((float)r, RECIP_27);   // XLA recip-mul
        const float tx = __fmul_rn((float)c, RECIP_27);
        const float ys = __fmul_rn(__fadd_rn(y1, __fmul_rn(ty, dy)), (float)(IMG_H - 1));
        const float xs = __fmul_rn(__fadd_rn(x1, __fmul_rn(tx, dx)), (float)(IMG_W - 1));
        const float y0f = floorf(ys), x0f = floorf(xs);
        const float fy = __fsub_rn(ys, y0f), fx = __fsub_rn(xs, x0f);
        int y0 = (int)y0f; y0 = y0 < 0 ? 0 : (y0 > IMG_H - 1 ? IMG_H - 1 : y0);
        int x0 = (int)x0f; x0 = x0 < 0 ? 0 : (x0 > IMG_W - 1 ? IMG_W - 1 : x0);
        const int y1i = min(y0 + 1, IMG_H - 1);
        const int x1i = min(x0 + 1, IMG_W - 1);

        const float m00 = masks_in[base + ((size_t)y0  * IMG_W + x0 ) * MAX_GT];
        const float m01 = masks_in[base + ((size_t)y0  * IMG_W + x1i) * MAX_GT];
        const float m10 = masks_in[base + ((size_t)y1i * IMG_W + x0 ) * MAX_GT];
        const float m11 = masks_in[base + ((size_t)y1i * IMG_W + x1i) * MAX_GT];

        const float ofy = __fsub_rn(1.0f, fy), ofx = __fsub_rn(1.0f, fx);
        const float t0 = __fmul_rn(__fmul_rn(m00, ofy), ofx);
        const float t1 = __fmul_rn(__fmul_rn(m01, ofy), fx);
        const float t2 = __fmul_rn(__fmul_rn(m10, fy),  ofx);
        const float t3 = __fmul_rn(__fmul_rn(m11, fy),  fx);
        const float val = __fadd_rn(__fadd_rn(__fadd_rn(t0, t1), t2), t3);
        dst[i] = rintf(val);   // jnp.round = half-to-even
    }
}

// ---------------------------------------------------------------------------
// Kernel 3: emit rois / class_ids / deltas
// ---------------------------------------------------------------------------
__global__ void __launch_bounds__(256)
k_emit(const float4* __restrict__ proposals,
       const int*    __restrict__ gt_cls,
       const float4* __restrict__ gt_boxes,
       const float*  __restrict__ std4,
       float* __restrict__ out) {
    const int b = blockIdx.x;
    const int tid = threadIdx.x;

    float* o_rois = out + OFF_ROIS;
    float* o_cls  = out + OFF_CLS;
    float* o_del  = out + OFF_DEL;

    if (tid < NUM_POS) {
        const unsigned long long key = g_ptop[b][tid];
        const int n = (int)(~(unsigned)key);
        const int v = ((unsigned)(key >> 32)) > 0x80000000u;
        const int g = g_pg[b][tid];
        const float vf = v ? 1.0f : 0.0f;

        const float4 p = proposals[b * N_PROP + n];
        const float b0 = p.x, b1 = p.y, b2 = p.z, b3 = p.w;

        float q0, q1, q2, q3;
        if (v) {
            const float4 q = gt_boxes[b * MAX_GT + g];
            q0 = q.x; q1 = q.y; q2 = q.z; q3 = q.w;
        } else {
            q0 = b0; q1 = b1; q2 = b2; q3 = b3;
        }

        const float h  = __fsub_rn(b2, b0), w  = __fsub_rn(b3, b1);
        const float cy = __fadd_rn(b0, __fmul_rn(0.5f, h));
        const float cx = __fadd_rn(b1, __fmul_rn(0.5f, w));
        const float gh = __fsub_rn(q2, q0), gw = __fsub_rn(q3, q1);
        const float gcy = __fadd_rn(q0, __fmul_rn(0.5f, gh));
        const float gcx = __fadd_rn(q1, __fmul_rn(0.5f, gw));

        float d0 = __fdiv_rn(__fsub_rn(gcy, cy), h);
        float d1 = __fdiv_rn(__fsub_rn(gcx, cx), w);
        float d2 = logf(__fdiv_rn(gh, h));
        float d3 = logf(__fdiv_rn(gw, w));
        d0 = __fmul_rn(__fdiv_rn(d0, std4[0]), vf);
        d1 = __fmul_rn(__fdiv_rn(d1, std4[1]), vf);
        d2 = __fmul_rn(__fdiv_rn(d2, std4[2]), vf);
        d3 = __fmul_rn(__fdiv_rn(d3, std4[3]), vf);

        float* rr = o_rois + (b * T_ROIS + tid) * 4;
        rr[0] = __fmul_rn(b0, vf); rr[1] = __fmul_rn(b1, vf);
        rr[2] = __fmul_rn(b2, vf); rr[3] = __fmul_rn(b3, vf);

        o_cls[b * T_ROIS + tid] = v ? (float)gt_cls[b * MAX_GT + g] : 0.0f;

        float* dd = o_del + (b * T_ROIS + tid) * 4;
        dd[0] = d0; dd[1] = d1; dd[2] = d2; dd[3] = d3;
    } else if (tid < T_ROIS) {
        const int j = tid - NUM_POS;
        const int P = g_P[b];
        const int tP = (int)__fmul_rn((float)P, RECIP_033);  // XLA recip-mul
        int need = tP - P;
        need = need < 0 ? 0 : (need > NUM_NEG ? NUM_NEG : need);

        const unsigned long long key = g_ntop[b][j];
        const int n = (int)(~(unsigned)key);
        const int v = (((unsigned)(key >> 32)) > 0x80000000u) && (j < need);
        const float vf = v ? 1.0f : 0.0f;
        const float4 p = proposals[b * N_PROP + n];

        float* rr = o_rois + (b * T_ROIS + tid) * 4;
        rr[0] = __fmul_rn(p.x, vf); rr[1] = __fmul_rn(p.y, vf);
        rr[2] = __fmul_rn(p.z, vf); rr[3] = __fmul_rn(p.w, vf);
        o_cls[b * T_ROIS + tid] = 0.0f;
        float* dd = o_del + (b * T_ROIS + tid) * 4;
        dd[0] = 0.f; dd[1] = 0.f; dd[2] = 0.f; dd[3] = 0.f;
    }
}

// ---------------------------------------------------------------------------
// Launch
// ---------------------------------------------------------------------------
extern "C" void kernel_launch(void* const* d_in, const int* in_sizes, int n_in,
                              void* d_out, int out_size) {
    const float* proposals = nullptr;
    const int*   cls       = nullptr;
    const float* gtb       = nullptr;
    const float* masks     = nullptr;
    const float* std4      = nullptr;
    for (int i = 0; i < n_in; ++i) {
        switch (in_sizes[i]) {
            case BATCH * N_PROP * 4:               proposals = (const float*)d_in[i]; break;
            case BATCH * MAX_GT:                   cls       = (const int*)  d_in[i]; break;
            case BATCH * MAX_GT * 4:               gtb       = (const float*)d_in[i]; break;
            case BATCH * IMG_H * IMG_W * MAX_GT:   masks     = (const float*)d_in[i]; break;
            case 4:                                std4      = (const float*)d_in[i]; break;
            default: break;
        }
    }

    // per-image kp/kn (pure function of seed 42)
    KeySet ks;
    for (int b = 0; b < BATCH; ++b) {
        unsigned kb0, kb1;
        tf2x32(0u, 42u, 0u, (unsigned)b, kb0, kb1);          // split(key(42),16)[b]
        tf2x32(kb0, kb1, 0u, 0u, ks.kp0[b], ks.kp1[b]);      // split(key)[0]
        tf2x32(kb0, kb1, 0u, 1u, ks.kn0[b], ks.kn1[b]);      // split(key)[1]
    }

    const float4* prop4 = (const float4*)proposals;
    const float4* gtb4  = (const float4*)gtb;
    float* out = (float*)d_out;

    k_select<<<2 * BATCH, 1024>>>(prop4, cls, gtb4, ks);
    k_mask<<<dim3(T_ROIS, BATCH), 256>>>(masks, out);       // depends on pos path only
    k_emit<<<BATCH, 256>>>(prop4, cls, gtb4, std4, out);    // tiny; after mask
}

// round 15
// speedup vs baseline: 1.4715x; 1.4715x over previous
#include <cuda_runtime.h>
#include <cuda_bf16.h>
#include <stdint.h>

// ---------------------------------------------------------------------------
// Problem constants
// ---------------------------------------------------------------------------
#define BATCH     16
#define N_PROP    2000
#define N_PAD     2048
#define MAX_GT    100
#define IMG_H     160
#define IMG_W     160
#define T_ROIS    200
#define NUM_POS   66
#define NUM_NEG   134
#define MH        28
#define MW        28

// output layout (float32, tuple order: rois, class_ids, deltas, masks)
#define OFF_ROIS  0
#define OFF_CLS   (BATCH * T_ROIS * 4)                 // 12800
#define OFF_DEL   (OFF_CLS + BATCH * T_ROIS)           // 16000
#define OFF_MASK  (OFF_DEL + BATCH * T_ROIS * 4)       // 28800

// XLA rewrites x / const -> x * (1/const); replicate for bit-exactness.
#define RECIP_033  (1.0f / 0.33f)
#define RECIP_27   (1.0f / 27.0f)

// ---------------------------------------------------------------------------
// Scratch (__device__ globals; no allocations allowed)
// ---------------------------------------------------------------------------
__device__ unsigned long long g_poskey[BATCH * N_PROP];
__device__ unsigned long long g_negkey[BATCH * N_PROP];
__device__ unsigned long long g_ptop[BATCH][NUM_POS];
__device__ unsigned long long g_ntop[BATCH][NUM_NEG];
__device__ int   g_pg[BATCH][NUM_POS];
__device__ int   g_P[BATCH];
__device__ float g_mbox[BATCH * NUM_POS * 4];
__device__ int   g_mg[BATCH * NUM_POS];
__device__ int   g_mv[BATCH * NUM_POS];

// ---------------------------------------------------------------------------
// JAX threefry2x32 (partitionable mode semantics)
// ---------------------------------------------------------------------------
__host__ __device__ __forceinline__ void tf2x32(unsigned k0, unsigned k1,
                                                unsigned x0, unsigned x1,
                                                unsigned &o0, unsigned &o1) {
    unsigned ks0 = k0, ks1 = k1, ks2 = k0 ^ k1 ^ 0x1BD11BDAu;
    x0 += ks0; x1 += ks1;
#define TFR(r) { x0 += x1; x1 = (x1 << (r)) | (x1 >> (32 - (r))); x1 ^= x0; }
    TFR(13) TFR(15) TFR(26) TFR(6)  x0 += ks1; x1 += ks2 + 1u;
    TFR(17) TFR(29) TFR(16) TFR(24) x0 += ks2; x1 += ks0 + 2u;
    TFR(13) TFR(15) TFR(26) TFR(6)  x0 += ks0; x1 += ks1 + 3u;
    TFR(17) TFR(29) TFR(16) TFR(24) x0 += ks1; x1 += ks2 + 4u;
    TFR(13) TFR(15) TFR(26) TFR(6)  x0 += ks2; x1 += ks0 + 5u;
#undef TFR
    o0 = x0; o1 = x1;
}

__device__ __forceinline__ float u01_from_bits(unsigned bits) {
    return __uint_as_float((bits >> 9) | 0x3f800000u) - 1.0f;
}

// order-preserving float->u32 + ~idx tiebreak (stable top_k when sorted desc)
__device__ __forceinline__ unsigned long long pack_key(float f, int idx) {
    unsigned u = __float_as_uint(f);
    u = (u & 0x80000000u) ? ~u : (u | 0x80000000u);
    return (((unsigned long long)u) << 32) | (unsigned)(~idx);
}

struct KeySet {
    unsigned kp0[BATCH], kp1[BATCH], kn0[BATCH], kn1[BATCH];
};

#define NAMED_BAR_256() asm volatile("bar.sync 1, 256;" ::: "memory")

// ---------------------------------------------------------------------------
// Kernel 1: pos/neg classification (division-free, exact) + sort keys.
// 4 threads per proposal, each covering 25 GTs. Wide grid (512 blocks).
//
// fl(inter/union) >= 0.5  <=>  2*inter >= union
//                          ||  (union - 2*inter) <= union * 2^-25
// ---------------------------------------------------------------------------
__global__ void __launch_bounds__(256)
k_score(const float4* __restrict__ proposals,
        const int*    __restrict__ gt_cls,
        const float4* __restrict__ gt_boxes,
        KeySet keys) {
    const int b = blockIdx.y;
    const int t = threadIdx.x;

    __shared__ float4 sg[MAX_GT];
    __shared__ float  sa[MAX_GT];
    __shared__ int    sv[MAX_GT];
    for (int i = t; i < MAX_GT; i += 256) {
        const float4 q = gt_boxes[b * MAX_GT + i];
        sg[i] = q;
        sa[i] = __fmul_rn(__fsub_rn(q.z, q.x), __fsub_rn(q.w, q.y));
        sv[i] = gt_cls[b * MAX_GT + i] > 0;
    }
    __syncthreads();

    const int n = blockIdx.x * 64 + (t >> 2);   // 64 proposals per block
    const int r = t & 3;
    if (n >= N_PROP) return;                    // whole-warp exits only

    const float4 p = proposals[b * N_PROP + n];
    const bool vp = (p.x != 0.f) || (p.y != 0.f) || (p.z != 0.f) || (p.w != 0.f);
    const float a1 = __fmul_rn(__fsub_rn(p.z, p.x), __fsub_rn(p.w, p.y));

    bool mypos = false;
    const int g0 = r * 25;
    #pragma unroll 5
    for (int k = 0; k < 25; ++k) {
        const int g = g0 + k;
        if (!sv[g]) continue;
        const float4 q = sg[g];
        const float ih = fmaxf(__fsub_rn(fminf(p.z, q.z), fmaxf(p.x, q.x)), 0.f);
        const float iw = fmaxf(__fsub_rn(fminf(p.w, q.w), fmaxf(p.y, q.y)), 0.f);
        const float inter = __fmul_rn(ih, iw);
        const float u = fmaxf(__fsub_rn(__fadd_rn(a1, sa[g]), inter), 1e-10f);
        const float t2 = __fmul_rn(2.0f, inter);           // exact
        mypos |= (t2 >= u) ||
                 (__fsub_rn(u, t2) <= __fmul_rn(u, 0x1p-25f));
    }

    const unsigned bal = __ballot_sync(0xFFFFFFFFu, mypos);
    const bool pos = ((bal >> ((t & 31) & ~3)) & 0xFu) != 0;   // quad any()

    unsigned o0, o1;
    if (r == 0) {
        tf2x32(keys.kp0[b], keys.kp1[b], 0u, (unsigned)n, o0, o1);
        g_poskey[b * N_PROP + n] =
            pack_key((pos && vp) ? u01_from_bits(o0 ^ o1) : -1.0f, n);
    } else if (r == 1) {
        tf2x32(keys.kn0[b], keys.kn1[b], 0u, (unsigned)n, o0, o1);
        g_negkey[b * N_PROP + n] =
            pack_key((!pos && vp) ? u01_from_bits(o0 ^ o1) : -1.0f, n);
    }
}

// ---------------------------------------------------------------------------
// full 2048 bitonic (descending) — exact fallback path only (512 threads)
// ---------------------------------------------------------------------------
__device__ __forceinline__ void bitonic_desc_2048(unsigned long long* s, int tid) {
    for (unsigned k = 2; k <= N_PAD; k <<= 1) {
        for (unsigned j = k >> 1; j > 0; j >>= 1) {
            __syncthreads();
            for (unsigned i = tid; i < N_PAD; i += 512) {
                const unsigned ixj = i ^ j;
                if (ixj > i) {
                    const unsigned long long a = s[i], c = s[ixj];
                    const bool swp = ((i & k) == 0) ? (a < c) : (a > c);
                    if (swp) { s[i] = c; s[ixj] = a; }
                }
            }
        }
    }
    __syncthreads();
}

// ---------------------------------------------------------------------------
// Kernel 2 (thin): 32 blocks = (image, list). Exact top-K radix select:
// histogram by top-11 key bits -> suffix scan -> compact <=256 candidates ->
// hybrid shfl/named-bar bitonic-256. Fallback: full 2048 bitonic.
// Pos blocks also: P, per-positive argmax (the only rounded divides),
// mask metadata.
// ---------------------------------------------------------------------------
__global__ void __launch_bounds__(512)
k_pick(const float4* __restrict__ proposals,
       const int*    __restrict__ gt_cls,
       const float4* __restrict__ gt_boxes) {
    const int b    = blockIdx.x >> 1;
    const int list = blockIdx.x & 1;
    const int K    = list ? NUM_NEG : NUM_POS;
    const int tid  = threadIdx.x;

    __shared__ unsigned long long s_keys[N_PAD];
    __shared__ unsigned s_hA[N_PAD];
    __shared__ unsigned s_hB[N_PAD];
    __shared__ unsigned long long s_cand[256];
    __shared__ unsigned s_cnt, s_T;
    __shared__ float4 sg[MAX_GT];
    __shared__ float  sa[MAX_GT];
    __shared__ int    sv[MAX_GT];

    const unsigned long long* src_g = list ? g_negkey : g_poskey;
    for (int i = tid; i < N_PAD; i += 512) {
        const unsigned long long key = (i < N_PROP) ? src_g[b * N_PROP + i] : 0ull;
        s_keys[i] = key;
        s_hA[i] = 0u;
    }
    if (!list) {   // pos blocks need GT data for the argmax
        for (int i = tid; i < MAX_GT; i += 512) {
            const float4 q = gt_boxes[b * MAX_GT + i];
            sg[i] = q;
            sa[i] = __fmul_rn(__fsub_rn(q.z, q.x), __fsub_rn(q.w, q.y));
            sv[i] = gt_cls[b * MAX_GT + i] > 0;
        }
    }
    if (tid == 0) s_cnt = 0u;
    __syncthreads();

    for (int i = tid; i < N_PAD; i += 512)
        atomicAdd(&s_hA[(unsigned)(s_keys[i] >> 53)], 1u);
    __syncthreads();

    // suffix counts: reverse + Hillis-Steele inclusive scan
    for (int i = tid; i < N_PAD; i += 512) s_hB[i] = s_hA[2047 - i];
    __syncthreads();
    unsigned *src = s_hB, *dst = s_hA;
    for (int off = 1; off < N_PAD; off <<= 1) {
        for (int i = tid; i < N_PAD; i += 512)
            dst[i] = src[i] + ((i >= off) ? src[i - off] : 0u);
        __syncthreads();
        unsigned* t = src; src = dst; dst = t;
    }
    // suffix(bkt) = src[2047 - bkt]

    // threshold bucket T: suffix(T) >= K, suffix(T+1) < K (unique)
    for (int i = tid; i < N_PAD; i += 512) {
        const unsigned Sb  = src[2047 - i];
        const unsigned Sb1 = (i == 2047) ? 0u : src[2046 - i];
        if (Sb >= (unsigned)K && Sb1 < (unsigned)K) s_T = (unsigned)i;
    }
    __syncthreads();
    const unsigned T = s_T;

    // compact candidates (buckets >= T)
    for (int i = tid; i < N_PAD; i += 512) {
        const unsigned long long key = s_keys[i];
        if ((unsigned)(key >> 53) >= T) {
            const unsigned p = atomicAdd(&s_cnt, 1u);
            if (p < 256u) s_cand[p] = key;
        }
    }
    __syncthreads();
    const unsigned cnt = s_cnt;

    const unsigned long long* res;
    if (cnt > 256u) {
        bitonic_desc_2048(s_keys, tid);   // exact fallback
        res = s_keys;
    } else {
        if (tid < 256 && (unsigned)tid >= cnt) s_cand[tid] = 0ull;
        __syncthreads();
        // hybrid bitonic-256 desc: j<=16 via shfl, j>=32 via smem + bar.sync 1,256
        if (tid < 256) {
            unsigned long long e = s_cand[tid];
            for (unsigned k = 2; k <= 256; k <<= 1) {
                for (unsigned j = k >> 1; j > 0; j >>= 1) {
                    const bool keepMax =
                        (((tid & k) == 0u) == ((tid & j) == 0u));
                    if (j <= 16) {
                        const unsigned long long p =
                            __shfl_xor_sync(0xFFFFFFFFu, e, j);
                        e = keepMax ? (e > p ? e : p) : (e < p ? e : p);
                    } else {
                        s_cand[tid] = e;
                        NAMED_BAR_256();
                        const unsigned long long p = s_cand[tid ^ j];
                        e = keepMax ? (e > p ? e : p) : (e < p ? e : p);
                        NAMED_BAR_256();
                    }
                }
            }
            s_cand[tid] = e;
        }
        __syncthreads();
        res = s_cand;
    }

    // ---- emit ----
    if (list) {
        if (tid < NUM_NEG) g_ntop[b][tid] = res[tid];
        return;
    }

    if (tid < NUM_POS) {
        const unsigned long long key = res[tid];
        const int n = (int)(~(unsigned)key);
        const int v = ((unsigned)(key >> 32)) > 0x80000000u;
        g_ptop[b][tid] = key;
        const float4 p = proposals[b * N_PROP + n];
        const int mi = b * NUM_POS + tid;
        g_mbox[mi * 4 + 0] = p.x; g_mbox[mi * 4 + 1] = p.y;
        g_mbox[mi * 4 + 2] = p.z; g_mbox[mi * 4 + 3] = p.w;
        g_mv[mi] = v;
    }
    if (tid == 0) {
        int P = 0;
        for (int i = 0; i < NUM_POS; ++i)
            P += (((unsigned)(res[i] >> 32)) > 0x80000000u);
        g_P[b] = P;
    }

    // warp-per-positive argmax over where(valid, fl(inter/union), -1)
    const int wid = tid >> 5, lane = tid & 31;   // 16 warps
    for (int slot = wid; slot < NUM_POS; slot += 16) {
        const int n = (int)(~(unsigned)res[slot]);
        const float4 p = proposals[b * N_PROP + n];
        const float a1 = __fmul_rn(__fsub_rn(p.z, p.x), __fsub_rn(p.w, p.y));

        float bestv = -2.0f; int bestg = 0;
        #pragma unroll 4
        for (int k = 0; k < 4; ++k) {
            const int g = lane + k * 32;
            if (g < MAX_GT) {
                float v = -1.0f;
                if (sv[g]) {
                    const float4 q = sg[g];
                    const float ih = fmaxf(__fsub_rn(fminf(p.z, q.z), fmaxf(p.x, q.x)), 0.f);
                    const float iw = fmaxf(__fsub_rn(fminf(p.w, q.w), fmaxf(p.y, q.y)), 0.f);
                    const float inter = __fmul_rn(ih, iw);
                    const float u = fmaxf(__fsub_rn(__fadd_rn(a1, sa[g]), inter), 1e-10f);
                    v = __fdiv_rn(inter, u);
                }
                if (v > bestv) { bestv = v; bestg = g; }   // ascending g: first-max
            }
        }
        #pragma unroll
        for (int off = 16; off; off >>= 1) {
            const float ov = __shfl_down_sync(0xFFFFFFFFu, bestv, off);
            const int   og = __shfl_down_sync(0xFFFFFFFFu, bestg, off);
            if (ov > bestv || (ov == bestv && og < bestg)) { bestv = ov; bestg = og; }
        }
        if (lane == 0) {
            g_pg[b][slot] = bestg;
            g_mg[b * NUM_POS + slot] = bestg;
        }
    }
}

// ---------------------------------------------------------------------------
// Kernel 3: mask crop_and_resize (tf bilinear) — 256 threads, pixel loop
// ---------------------------------------------------------------------------
__global__ void __launch_bounds__(256)
k_mask(const float* __restrict__ masks_in,
       float* __restrict__ out) {
    const int slot = blockIdx.x;
    const int b    = blockIdx.y;
    float* dst = out + OFF_MASK + (size_t)(b * T_ROIS + slot) * (MH * MW);
    const int tid = threadIdx.x;

    int v = 0, g = 0;
    float y1 = 0.f, x1 = 0.f, y2 = 0.f, x2 = 0.f;
    if (slot < NUM_POS) {
        const int mi = b * NUM_POS + slot;
        v = g_mv[mi];
        g = g_mg[mi];
        y1 = g_mbox[mi * 4 + 0]; x1 = g_mbox[mi * 4 + 1];
        y2 = g_mbox[mi * 4 + 2]; x2 = g_mbox[mi * 4 + 3];
    }
    if (!v) {
        for (int i = tid; i < MH * MW; i += 256) dst[i] = 0.0f;
        return;
    }

    const size_t base = (size_t)b * IMG_H * IMG_W * MAX_GT + g;
    const float dy = __fsub_rn(y2, y1);
    const float dx = __fsub_rn(x2, x1);

    for (int i = tid; i < MH * MW; i += 256) {
        const int r = i / MW, c = i % MW;
        const float ty = __fmul_rn((float)r, RECIP_27);   // XLA recip-mul
        const float tx = __fmul_rn((float)c, RECIP_27);
        const float ys = __fmul_rn(__fadd_rn(y1, __fmul_rn(ty, dy)), (float)(IMG_H - 1));
        const float xs = __fmul_rn(__fadd_rn(x1, __fmul_rn(tx, dx)), (float)(IMG_W - 1));
        const float y0f = floorf(ys), x0f = floorf(xs);
        const float fy = __fsub_rn(ys, y0f), fx = __fsub_rn(xs, x0f);
        int y0 = (int)y0f; y0 = y0 < 0 ? 0 : (y0 > IMG_H - 1 ? IMG_H - 1 : y0);
        int x0 = (int)x0f; x0 = x0 < 0 ? 0 : (x0 > IMG_W - 1 ? IMG_W - 1 : x0);
        const int y1i = min(y0 + 1, IMG_H - 1);
        const int x1i = min(x0 + 1, IMG_W - 1);

        const float m00 = masks_in[base + ((size_t)y0  * IMG_W + x0 ) * MAX_GT];
        const float m01 = masks_in[base + ((size_t)y0  * IMG_W + x1i) * MAX_GT];
        const float m10 = masks_in[base + ((size_t)y1i * IMG_W + x0 ) * MAX_GT];
        const float m11 = masks_in[base + ((size_t)y1i * IMG_W + x1i) * MAX_GT];

        const float ofy = __fsub_rn(1.0f, fy), ofx = __fsub_rn(1.0f, fx);
        const float t0 = __fmul_rn(__fmul_rn(m00, ofy), ofx);
        const float t1 = __fmul_rn(__fmul_rn(m01, ofy), fx);
        const float t2 = __fmul_rn(__fmul_rn(m10, fy),  ofx);
        const float t3 = __fmul_rn(__fmul_rn(m11, fy),  fx);
        const float val = __fadd_rn(__fadd_rn(__fadd_rn(t0, t1), t2), t3);
        dst[i] = rintf(val);   // jnp.round = half-to-even
    }
}

// ---------------------------------------------------------------------------
// Kernel 4: emit rois / class_ids / deltas
// ---------------------------------------------------------------------------
__global__ void __launch_bounds__(256)
k_emit(const float4* __restrict__ proposals,
       const int*    __restrict__ gt_cls,
       const float4* __restrict__ gt_boxes,
       const float*  __restrict__ std4,
       float* __restrict__ out) {
    const int b = blockIdx.x;
    const int tid = threadIdx.x;

    float* o_rois = out + OFF_ROIS;
    float* o_cls  = out + OFF_CLS;
    float* o_del  = out + OFF_DEL;

    if (tid < NUM_POS) {
        const unsigned long long key = g_ptop[b][tid];
        const int n = (int)(~(unsigned)key);
        const int v = ((unsigned)(key >> 32)) > 0x80000000u;
        const int g = g_pg[b][tid];
        const float vf = v ? 1.0f : 0.0f;

        const float4 p = proposals[b * N_PROP + n];
        const float b0 = p.x, b1 = p.y, b2 = p.z, b3 = p.w;

        float q0, q1, q2, q3;
        if (v) {
            const float4 q = gt_boxes[b * MAX_GT + g];
            q0 = q.x; q1 = q.y; q2 = q.z; q3 = q.w;
        } else {
            q0 = b0; q1 = b1; q2 = b2; q3 = b3;
        }

        const float h  = __fsub_rn(b2, b0), w  = __fsub_rn(b3, b1);
        const float cy = __fadd_rn(b0, __fmul_rn(0.5f, h));
        const float cx = __fadd_rn(b1, __fmul_rn(0.5f, w));
        const float gh = __fsub_rn(q2, q0), gw = __fsub_rn(q3, q1);
        const float gcy = __fadd_rn(q0, __fmul_rn(0.5f, gh));
        const float gcx = __fadd_rn(q1, __fmul_rn(0.5f, gw));

        float d0 = __fdiv_rn(__fsub_rn(gcy, cy), h);
        float d1 = __fdiv_rn(__fsub_rn(gcx, cx), w);
        float d2 = logf(__fdiv_rn(gh, h));
        float d3 = logf(__fdiv_rn(gw, w));
        d0 = __fmul_rn(__fdiv_rn(d0, std4[0]), vf);
        d1 = __fmul_rn(__fdiv_rn(d1, std4[1]), vf);
        d2 = __fmul_rn(__fdiv_rn(d2, std4[2]), vf);
        d3 = __fmul_rn(__fdiv_rn(d3, std4[3]), vf);

        float* rr = o_rois + (b * T_ROIS + tid) * 4;
        rr[0] = __fmul_rn(b0, vf); rr[1] = __fmul_rn(b1, vf);
        rr[2] = __fmul_rn(b2, vf); rr[3] = __fmul_rn(b3, vf);

        o_cls[b * T_ROIS + tid] = v ? (float)gt_cls[b * MAX_GT + g] : 0.0f;

        float* dd = o_del + (b * T_ROIS + tid) * 4;
        dd[0] = d0; dd[1] = d1; dd[2] = d2; dd[3] = d3;
    } else if (tid < T_ROIS) {
        const int j = tid - NUM_POS;
        const int P = g_P[b];
        const int tP = (int)__fmul_rn((float)P, RECIP_033);  // XLA recip-mul
        int need = tP - P;
        need = need < 0 ? 0 : (need > NUM_NEG ? NUM_NEG : need);

        const unsigned long long key = g_ntop[b][j];
        const int n = (int)(~(unsigned)key);
        const int v = (((unsigned)(key >> 32)) > 0x80000000u) && (j < need);
        const float vf = v ? 1.0f : 0.0f;
        const float4 p = proposals[b * N_PROP + n];

        float* rr = o_rois + (b * T_ROIS + tid) * 4;
        rr[0] = __fmul_rn(p.x, vf); rr[1] = __fmul_rn(p.y, vf);
        rr[2] = __fmul_rn(p.z, vf); rr[3] = __fmul_rn(p.w, vf);
        o_cls[b * T_ROIS + tid] = 0.0f;
        float* dd = o_del + (b * T_ROIS + tid) * 4;
        dd[0] = 0.f; dd[1] = 0.f; dd[2] = 0.f; dd[3] = 0.f;
    }
}

// ---------------------------------------------------------------------------
// Launch
// ---------------------------------------------------------------------------
extern "C" void kernel_launch(void* const* d_in, const int* in_sizes, int n_in,
                              void* d_out, int out_size) {
    const float* proposals = nullptr;
    const int*   cls       = nullptr;
    const float* gtb       = nullptr;
    const float* masks     = nullptr;
    const float* std4      = nullptr;
    for (int i = 0; i < n_in; ++i) {
        switch (in_sizes[i]) {
            case BATCH * N_PROP * 4:               proposals = (const float*)d_in[i]; break;
            case BATCH * MAX_GT:                   cls       = (const int*)  d_in[i]; break;
            case BATCH * MAX_GT * 4:               gtb       = (const float*)d_in[i]; break;
            case BATCH * IMG_H * IMG_W * MAX_GT:   masks     = (const float*)d_in[i]; break;
            case 4:                                std4      = (const float*)d_in[i]; break;
            default: break;
        }
    }

    // per-image kp/kn (pure function of seed 42)
    KeySet ks;
    for (int b = 0; b < BATCH; ++b) {
        unsigned kb0, kb1;
        tf2x32(0u, 42u, 0u, (unsigned)b, kb0, kb1);          // split(key(42),16)[b]
        tf2x32(kb0, kb1, 0u, 0u, ks.kp0[b], ks.kp1[b]);      // split(key)[0]
        tf2x32(kb0, kb1, 0u, 1u, ks.kn0[b], ks.kn1[b]);      // split(key)[1]
    }

    const float4* prop4 = (const float4*)proposals;
    const float4* gtb4  = (const float4*)gtb;
    float* out = (float*)d_out;

    k_score<<<dim3(32, BATCH), 256>>>(prop4, cls, gtb4, ks);
    k_pick<<<2 * BATCH, 512>>>(prop4, cls, gtb4);
    k_mask<<<dim3(T_ROIS, BATCH), 256>>>(masks, out);   // depends on pos path only
    k_emit<<<BATCH, 256>>>(prop4, cls, gtb4, std4, out);
}

// round 17
// speedup vs baseline: 1.6327x; 1.1096x over previous
#include <cuda_runtime.h>
#include <cuda_bf16.h>
#include <stdint.h>

// ---------------------------------------------------------------------------
// Problem constants
// ---------------------------------------------------------------------------
#define BATCH     16
#define N_PROP    2000
#define N_PAD     2048
#define MAX_GT    100
#define IMG_H     160
#define IMG_W     160
#define T_ROIS    200
#define NUM_POS   66
#define NUM_NEG   134
#define MH        28
#define MW        28
#define NBLK      32          // x-blocks in k_score (64 proposals each)

// output layout (float32, tuple order: rois, class_ids, deltas, masks)
#define OFF_ROIS  0
#define OFF_CLS   (BATCH * T_ROIS * 4)                 // 12800
#define OFF_DEL   (OFF_CLS + BATCH * T_ROIS)           // 16000
#define OFF_MASK  (OFF_DEL + BATCH * T_ROIS * 4)       // 28800

// XLA rewrites x / const -> x * (1/const); replicate for bit-exactness.
#define RECIP_033  (1.0f / 0.33f)
#define RECIP_27   (1.0f / 27.0f)

// ---------------------------------------------------------------------------
// Scratch (__device__ globals; no allocations allowed)
// ---------------------------------------------------------------------------
__device__ unsigned long long g_poskey[BATCH * N_PROP];
__device__ unsigned long long g_negkey[BATCH * N_PROP];
__device__ int   g_pcount[BATCH][NBLK];   // partial (pos&&valid&&score>0) counts
__device__ float g_mbox[BATCH * NUM_POS * 4];
__device__ int   g_mg[BATCH * NUM_POS];
__device__ int   g_mv[BATCH * NUM_POS];

// ---------------------------------------------------------------------------
// JAX threefry2x32 (partitionable mode semantics)
// ---------------------------------------------------------------------------
__host__ __device__ __forceinline__ void tf2x32(unsigned k0, unsigned k1,
                                                unsigned x0, unsigned x1,
                                                unsigned &o0, unsigned &o1) {
    unsigned ks0 = k0, ks1 = k1, ks2 = k0 ^ k1 ^ 0x1BD11BDAu;
    x0 += ks0; x1 += ks1;
#define TFR(r) { x0 += x1; x1 = (x1 << (r)) | (x1 >> (32 - (r))); x1 ^= x0; }
    TFR(13) TFR(15) TFR(26) TFR(6)  x0 += ks1; x1 += ks2 + 1u;
    TFR(17) TFR(29) TFR(16) TFR(24) x0 += ks2; x1 += ks0 + 2u;
    TFR(13) TFR(15) TFR(26) TFR(6)  x0 += ks0; x1 += ks1 + 3u;
    TFR(17) TFR(29) TFR(16) TFR(24) x0 += ks1; x1 += ks2 + 4u;
    TFR(13) TFR(15) TFR(26) TFR(6)  x0 += ks2; x1 += ks0 + 5u;
#undef TFR
    o0 = x0; o1 = x1;
}

__device__ __forceinline__ float u01_from_bits(unsigned bits) {
    return __uint_as_float((bits >> 9) | 0x3f800000u) - 1.0f;
}

// order-preserving float->u32 + ~idx tiebreak (stable top_k when sorted desc)
__device__ __forceinline__ unsigned long long pack_key(float f, int idx) {
    unsigned u = __float_as_uint(f);
    u = (u & 0x80000000u) ? ~u : (u | 0x80000000u);
    return (((unsigned long long)u) << 32) | (unsigned)(~idx);
}

struct KeySet {
    unsigned kp0[BATCH], kp1[BATCH], kn0[BATCH], kn1[BATCH];
};

#define NAMED_BAR_256() asm volatile("bar.sync 1, 256;" ::: "memory")

// ---------------------------------------------------------------------------
// Kernel 1: pos/neg classification (division-free, exact) + sort keys +
// per-block count of (pos && valid && score>0). 4 threads/proposal.
// ---------------------------------------------------------------------------
__global__ void __launch_bounds__(256)
k_score(const float4* __restrict__ proposals,
        const int*    __restrict__ gt_cls,
        const float4* __restrict__ gt_boxes,
        KeySet keys) {
    const int b = blockIdx.y;
    const int t = threadIdx.x;

    __shared__ float4 sg[MAX_GT];
    __shared__ float  sa[MAX_GT];
    __shared__ int    sv[MAX_GT];
    for (int i = t; i < MAX_GT; i += 256) {
        const float4 q = gt_boxes[b * MAX_GT + i];
        sg[i] = q;
        sa[i] = __fmul_rn(__fsub_rn(q.z, q.x), __fsub_rn(q.w, q.y));
        sv[i] = gt_cls[b * MAX_GT + i] > 0;
    }
    __syncthreads();

    const int n = blockIdx.x * 64 + (t >> 2);   // 64 proposals per block
    const int r = t & 3;

    bool countme = false;
    if (n < N_PROP) {
        const float4 p = proposals[b * N_PROP + n];
        const bool vp = (p.x != 0.f) || (p.y != 0.f) || (p.z != 0.f) || (p.w != 0.f);
        const float a1 = __fmul_rn(__fsub_rn(p.z, p.x), __fsub_rn(p.w, p.y));

        bool mypos = false;
        const int g0 = r * 25;
        #pragma unroll 5
        for (int k = 0; k < 25; ++k) {
            const int g = g0 + k;
            if (!sv[g]) continue;
            const float4 q = sg[g];
            const float ih = fmaxf(__fsub_rn(fminf(p.z, q.z), fmaxf(p.x, q.x)), 0.f);
            const float iw = fmaxf(__fsub_rn(fminf(p.w, q.w), fmaxf(p.y, q.y)), 0.f);
            const float inter = __fmul_rn(ih, iw);
            const float u = fmaxf(__fsub_rn(__fadd_rn(a1, sa[g]), inter), 1e-10f);
            const float t2 = __fmul_rn(2.0f, inter);           // exact
            // fl(inter/u) >= 0.5 <=> t2 >= u || (u - t2) <= u*2^-25 (exact)
            mypos |= (t2 >= u) ||
                     (__fsub_rn(u, t2) <= __fmul_rn(u, 0x1p-25f));
        }

        const unsigned bal = __ballot_sync(0xFFFFFFFFu, mypos);
        const bool pos = ((bal >> ((t & 31) & ~3)) & 0xFu) != 0;   // quad any()

        unsigned o0, o1;
        if (r == 0) {
            tf2x32(keys.kp0[b], keys.kp1[b], 0u, (unsigned)n, o0, o1);
            const float up = u01_from_bits(o0 ^ o1);
            g_poskey[b * N_PROP + n] =
                pack_key((pos && vp) ? up : -1.0f, n);
            countme = pos && vp && (up > 0.0f);    // == "score > 0" candidate
        } else if (r == 1) {
            tf2x32(keys.kn0[b], keys.kn1[b], 0u, (unsigned)n, o0, o1);
            g_negkey[b * N_PROP + n] =
                pack_key((!pos && vp) ? u01_from_bits(o0 ^ o1) : -1.0f, n);
        }
    }

    const int cnt = __syncthreads_count(countme);
    if (t == 0) g_pcount[b][blockIdx.x] = cnt;
}

// ---------------------------------------------------------------------------
// full 2048 bitonic (descending) — exact fallback path only (512 threads)
// ---------------------------------------------------------------------------
__device__ __forceinline__ void bitonic_desc_2048(unsigned long long* s, int tid) {
    for (unsigned k = 2; k <= N_PAD; k <<= 1) {
        for (unsigned j = k >> 1; j > 0; j >>= 1) {
            __syncthreads();
            for (unsigned i = tid; i < N_PAD; i += 512) {
                const unsigned ixj = i ^ j;
                if (ixj > i) {
                    const unsigned long long a = s[i], c = s[ixj];
                    const bool swp = ((i & k) == 0) ? (a < c) : (a > c);
                    if (swp) { s[i] = c; s[ixj] = a; }
                }
            }
        }
    }
    __syncthreads();
}

// ---------------------------------------------------------------------------
// Kernel 2: 32 blocks = (image, list). Exact top-K radix select + FULL
// emission (no separate emit kernel):
//  * neg blocks: compute P from g_pcount, need, write neg rows.
//  * pos blocks: argmax per positive (the only rounded divides), write pos
//    rois/cls/deltas + mask metadata.
// ---------------------------------------------------------------------------
__global__ void __launch_bounds__(512)
k_pick(const float4* __restrict__ proposals,
       const int*    __restrict__ gt_cls,
       const float4* __restrict__ gt_boxes,
       const float*  __restrict__ std4,
       float* __restrict__ out) {
    const int b    = blockIdx.x >> 1;
    const int list = blockIdx.x & 1;
    const int K    = list ? NUM_NEG : NUM_POS;
    const int tid  = threadIdx.x;

    __shared__ unsigned long long s_keys[N_PAD];
    __shared__ unsigned s_hA[N_PAD];
    __shared__ unsigned s_hB[N_PAD];
    __shared__ unsigned long long s_cand[256];
    __shared__ unsigned s_cnt, s_T;
    __shared__ float4 sg[MAX_GT];
    __shared__ float  sa[MAX_GT];
    __shared__ int    sv[MAX_GT];
    __shared__ int    s_pg[NUM_POS];

    const unsigned long long* src_g = list ? g_negkey : g_poskey;
    for (int i = tid; i < N_PAD; i += 512) {
        const unsigned long long key = (i < N_PROP) ? src_g[b * N_PROP + i] : 0ull;
        s_keys[i] = key;
        s_hA[i] = 0u;
    }
    if (!list) {   // pos blocks need GT data for the argmax
        for (int i = tid; i < MAX_GT; i += 512) {
            const float4 q = gt_boxes[b * MAX_GT + i];
            sg[i] = q;
            sa[i] = __fmul_rn(__fsub_rn(q.z, q.x), __fsub_rn(q.w, q.y));
            sv[i] = gt_cls[b * MAX_GT + i] > 0;
        }
    }
    if (tid == 0) s_cnt = 0u;
    __syncthreads();

    for (int i = tid; i < N_PAD; i += 512)
        atomicAdd(&s_hA[(unsigned)(s_keys[i] >> 53)], 1u);
    __syncthreads();

    // suffix counts: reverse + Hillis-Steele inclusive scan
    for (int i = tid; i < N_PAD; i += 512) s_hB[i] = s_hA[2047 - i];
    __syncthreads();
    unsigned *src = s_hB, *dst = s_hA;
    for (int off = 1; off < N_PAD; off <<= 1) {
        for (int i = tid; i < N_PAD; i += 512)
            dst[i] = src[i] + ((i >= off) ? src[i - off] : 0u);
        __syncthreads();
        unsigned* t = src; src = dst; dst = t;
    }
    // suffix(bkt) = src[2047 - bkt]

    // threshold bucket T: suffix(T) >= K, suffix(T+1) < K (unique)
    for (int i = tid; i < N_PAD; i += 512) {
        const unsigned Sb  = src[2047 - i];
        const unsigned Sb1 = (i == 2047) ? 0u : src[2046 - i];
        if (Sb >= (unsigned)K && Sb1 < (unsigned)K) s_T = (unsigned)i;
    }
    __syncthreads();
    const unsigned T = s_T;

    // compact candidates (buckets >= T)
    for (int i = tid; i < N_PAD; i += 512) {
        const unsigned long long key = s_keys[i];
        if ((unsigned)(key >> 53) >= T) {
            const unsigned p = atomicAdd(&s_cnt, 1u);
            if (p < 256u) s_cand[p] = key;
        }
    }
    __syncthreads();
    const unsigned cnt = s_cnt;

    const unsigned long long* res;
    if (cnt > 256u) {
        bitonic_desc_2048(s_keys, tid);   // exact fallback
        res = s_keys;
    } else {
        if (tid < 256 && (unsigned)tid >= cnt) s_cand[tid] = 0ull;
        __syncthreads();
        // hybrid bitonic-256 desc: j<=16 via shfl, j>=32 via smem + bar.sync 1,256
        if (tid < 256) {
            unsigned long long e = s_cand[tid];
            for (unsigned k = 2; k <= 256; k <<= 1) {
                for (unsigned j = k >> 1; j > 0; j >>= 1) {
                    const bool keepMax =
                        (((tid & k) == 0u) == ((tid & j) == 0u));
                    if (j <= 16) {
                        const unsigned long long p =
                            __shfl_xor_sync(0xFFFFFFFFu, e, j);
                        e = keepMax ? (e > p ? e : p) : (e < p ? e : p);
                    } else {
                        s_cand[tid] = e;
                        NAMED_BAR_256();
                        const unsigned long long p = s_cand[tid ^ j];
                        e = keepMax ? (e > p ? e : p) : (e < p ? e : p);
                        NAMED_BAR_256();
                    }
                }
            }
            s_cand[tid] = e;
        }
        __syncthreads();
        res = s_cand;
    }

    float* o_rois = out + OFF_ROIS;
    float* o_cls  = out + OFF_CLS;
    float* o_del  = out + OFF_DEL;

    // =================== negative blocks: emit neg rows ===================
    if (list) {
        // P = min(total (pos && valid && score>0), NUM_POS)
        int pc = (tid < NBLK) ? g_pcount[b][tid] : 0;
        #pragma unroll
        for (int off = 16; off; off >>= 1)
            pc += __shfl_down_sync(0xFFFFFFFFu, pc, off);
        __shared__ int s_P;
        if (tid == 0) s_P = (pc < NUM_POS) ? pc : NUM_POS;
        __syncthreads();
        const int P = s_P;
        const int tP = (int)__fmul_rn((float)P, RECIP_033);  // XLA recip-mul
        int need = tP - P;
        need = need < 0 ? 0 : (need > NUM_NEG ? NUM_NEG : need);

        if (tid < NUM_NEG) {
            const int slot = NUM_POS + tid;
            const unsigned long long key = res[tid];
            const int n = (int)(~(unsigned)key);
            const int v = (((unsigned)(key >> 32)) > 0x80000000u) && (tid < need);
            const float vf = v ? 1.0f : 0.0f;
            const float4 p = proposals[b * N_PROP + n];

            float* rr = o_rois + (b * T_ROIS + slot) * 4;
            rr[0] = __fmul_rn(p.x, vf); rr[1] = __fmul_rn(p.y, vf);
            rr[2] = __fmul_rn(p.z, vf); rr[3] = __fmul_rn(p.w, vf);
            o_cls[b * T_ROIS + slot] = 0.0f;
            float* dd = o_del + (b * T_ROIS + slot) * 4;
            dd[0] = 0.f; dd[1] = 0.f; dd[2] = 0.f; dd[3] = 0.f;
        }
        return;
    }

    // =================== positive block: argmax + emit ===================
    // warp-per-positive argmax over where(valid, fl(inter/union), -1)
    const int wid = tid >> 5, lane = tid & 31;   // 16 warps
    for (int slot = wid; slot < NUM_POS; slot += 16) {
        const int n = (int)(~(unsigned)res[slot]);
        const float4 p = proposals[b * N_PROP + n];
        const float a1 = __fmul_rn(__fsub_rn(p.z, p.x), __fsub_rn(p.w, p.y));

        float bestv = -2.0f; int bestg = 0;
        #pragma unroll 4
        for (int k = 0; k < 4; ++k) {
            const int g = lane + k * 32;
            if (g < MAX_GT) {
                float v = -1.0f;
                if (sv[g]) {
                    const float4 q = sg[g];
                    const float ih = fmaxf(__fsub_rn(fminf(p.z, q.z), fmaxf(p.x, q.x)), 0.f);
                    const float iw = fmaxf(__fsub_rn(fminf(p.w, q.w), fmaxf(p.y, q.y)), 0.f);
                    const float inter = __fmul_rn(ih, iw);
                    const float u = fmaxf(__fsub_rn(__fadd_rn(a1, sa[g]), inter), 1e-10f);
                    v = __fdiv_rn(inter, u);
                }
                if (v > bestv) { bestv = v; bestg = g; }   // ascending g: first-max
            }
        }
        #pragma unroll
        for (int off = 16; off; off >>= 1) {
            const float ov = __shfl_down_sync(0xFFFFFFFFu, bestv, off);
            const int   og = __shfl_down_sync(0xFFFFFFFFu, bestg, off);
            if (ov > bestv || (ov == bestv && og < bestg)) { bestv = ov; bestg = og; }
        }
        if (lane == 0) s_pg[slot] = bestg;
    }
    __syncthreads();

    if (tid < NUM_POS) {
        const unsigned long long key = res[tid];
        const int n = (int)(~(unsigned)key);
        const int v = ((unsigned)(key >> 32)) > 0x80000000u;
        const int g = s_pg[tid];
        const float vf = v ? 1.0f : 0.0f;

        const float4 p = proposals[b * N_PROP + n];
        const float b0 = p.x, b1 = p.y, b2 = p.z, b3 = p.w;

        float q0, q1, q2, q3;
        if (v) {
            const float4 q = sg[g];
            q0 = q.x; q1 = q.y; q2 = q.z; q3 = q.w;
        } else {
            q0 = b0; q1 = b1; q2 = b2; q3 = b3;
        }

        const float h  = __fsub_rn(b2, b0), w  = __fsub_rn(b3, b1);
        const float cy = __fadd_rn(b0, __fmul_rn(0.5f, h));
        const float cx = __fadd_rn(b1, __fmul_rn(0.5f, w));
        const float gh = __fsub_rn(q2, q0), gw = __fsub_rn(q3, q1);
        const float gcy = __fadd_rn(q0, __fmul_rn(0.5f, gh));
        const float gcx = __fadd_rn(q1, __fmul_rn(0.5f, gw));

        float d0 = __fdiv_rn(__fsub_rn(gcy, cy), h);
        float d1 = __fdiv_rn(__fsub_rn(gcx, cx), w);
        float d2 = logf(__fdiv_rn(gh, h));
        float d3 = logf(__fdiv_rn(gw, w));
        d0 = __fmul_rn(__fdiv_rn(d0, std4[0]), vf);
        d1 = __fmul_rn(__fdiv_rn(d1, std4[1]), vf);
        d2 = __fmul_rn(__fdiv_rn(d2, std4[2]), vf);
        d3 = __fmul_rn(__fdiv_rn(d3, std4[3]), vf);

        float* rr = o_rois + (b * T_ROIS + tid) * 4;
        rr[0] = __fmul_rn(b0, vf); rr[1] = __fmul_rn(b1, vf);
        rr[2] = __fmul_rn(b2, vf); rr[3] = __fmul_rn(b3, vf);

        o_cls[b * T_ROIS + tid] = v ? (float)gt_cls[b * MAX_GT + g] : 0.0f;

        float* dd = o_del + (b * T_ROIS + tid) * 4;
        dd[0] = d0; dd[1] = d1; dd[2] = d2; dd[3] = d3;

        const int mi = b * NUM_POS + tid;
        g_mbox[mi * 4 + 0] = b0; g_mbox[mi * 4 + 1] = b1;
        g_mbox[mi * 4 + 2] = b2; g_mbox[mi * 4 + 3] = b3;
        g_mg[mi] = g;
        g_mv[mi] = v;
    }
}

// ---------------------------------------------------------------------------
// Kernel 3: mask crop_and_resize (tf bilinear) — 256 threads, pixel loop
// ---------------------------------------------------------------------------
__global__ void __launch_bounds__(256)
k_mask(const float* __restrict__ masks_in,
       float* __restrict__ out) {
    const int slot = blockIdx.x;
    const int b    = blockIdx.y;
    float* dst = out + OFF_MASK + (size_t)(b * T_ROIS + slot) * (MH * MW);
    const int tid = threadIdx.x;

    int v = 0, g = 0;
    float y1 = 0.f, x1 = 0.f, y2 = 0.f, x2 = 0.f;
    if (slot < NUM_POS) {
        const int mi = b * NUM_POS + slot;
        v = g_mv[mi];
        g = g_mg[mi];
        y1 = g_mbox[mi * 4 + 0]; x1 = g_mbox[mi * 4 + 1];
        y2 = g_mbox[mi * 4 + 2]; x2 = g_mbox[mi * 4 + 3];
    }
    if (!v) {
        for (int i = tid; i < MH * MW; i += 256) dst[i] = 0.0f;
        return;
    }

    const size_t base = (size_t)b * IMG_H * IMG_W * MAX_GT + g;
    const float dy = __fsub_rn(y2, y1);
    const float dx = __fsub_rn(x2, x1);

    for (int i = tid; i < MH * MW; i += 256) {
        const int r = i / MW, c = i % MW;
        const float ty = __fmul_rn((float)r, RECIP_27);   // XLA recip-mul
        const float tx = __fmul_rn((float)c, RECIP_27);
        const float ys = __fmul_rn(__fadd_rn(y1, __fmul_rn(ty, dy)), (float)(IMG_H - 1));
        const float xs = __fmul_rn(__fadd_rn(x1, __fmul_rn(tx, dx)), (float)(IMG_W - 1));
        const float y0f = floorf(ys), x0f = floorf(xs);
        const float fy = __fsub_rn(ys, y0f), fx = __fsub_rn(xs, x0f);
        int y0 = (int)y0f; y0 = y0 < 0 ? 0 : (y0 > IMG_H - 1 ? IMG_H - 1 : y0);
        int x0 = (int)x0f; x0 = x0 < 0 ? 0 : (x0 > IMG_W - 1 ? IMG_W - 1 : x0);
        const int y1i = min(y0 + 1, IMG_H - 1);
        const int x1i = min(x0 + 1, IMG_W - 1);

        const float m00 = masks_in[base + ((size_t)y0  * IMG_W + x0 ) * MAX_GT];
        const float m01 = masks_in[base + ((size_t)y0  * IMG_W + x1i) * MAX_GT];
        const float m10 = masks_in[base + ((size_t)y1i * IMG_W + x0 ) * MAX_GT];
        const float m11 = masks_in[base + ((size_t)y1i * IMG_W + x1i) * MAX_GT];

        const float ofy = __fsub_rn(1.0f, fy), ofx = __fsub_rn(1.0f, fx);
        const float t0 = __fmul_rn(__fmul_rn(m00, ofy), ofx);
        const float t1 = __fmul_rn(__fmul_rn(m01, ofy), fx);
        const float t2 = __fmul_rn(__fmul_rn(m10, fy),  ofx);
        const float t3 = __fmul_rn(__fmul_rn(m11, fy),  fx);
        const float val = __fadd_rn(__fadd_rn(__fadd_rn(t0, t1), t2), t3);
        dst[i] = rintf(val);   // jnp.round = half-to-even
    }
}

// ---------------------------------------------------------------------------
// Launch
// ---------------------------------------------------------------------------
extern "C" void kernel_launch(void* const* d_in, const int* in_sizes, int n_in,
                              void* d_out, int out_size) {
    const float* proposals = nullptr;
    const int*   cls       = nullptr;
    const float* gtb       = nullptr;
    const float* masks     = nullptr;
    const float* std4      = nullptr;
    for (int i = 0; i < n_in; ++i) {
        switch (in_sizes[i]) {
            case BATCH * N_PROP * 4:               proposals = (const float*)d_in[i]; break;
            case BATCH * MAX_GT:                   cls       = (const int*)  d_in[i]; break;
            case BATCH * MAX_GT * 4:               gtb       = (const float*)d_in[i]; break;
            case BATCH * IMG_H * IMG_W * MAX_GT:   masks     = (const float*)d_in[i]; break;
            case 4:                                std4      = (const float*)d_in[i]; break;
            default: break;
        }
    }

    // per-image kp/kn (pure function of seed 42)
    KeySet ks;
    for (int b = 0; b < BATCH; ++b) {
        unsigned kb0, kb1;
        tf2x32(0u, 42u, 0u, (unsigned)b, kb0, kb1);          // split(key(42),16)[b]
        tf2x32(kb0, kb1, 0u, 0u, ks.kp0[b], ks.kp1[b]);      // split(key)[0]
        tf2x32(kb0, kb1, 0u, 1u, ks.kn0[b], ks.kn1[b]);      // split(key)[1]
    }

    const float4* prop4 = (const float4*)proposals;
    const float4* gtb4  = (const float4*)gtb;
    float* out = (float*)d_out;

    k_score<<<dim3(NBLK, BATCH), 256>>>(prop4, cls, gtb4, ks);
    k_pick<<<2 * BATCH, 512>>>(prop4, cls, gtb4, std4, out);
    k_mask<<<dim3(T_ROIS, BATCH), 256>>>(masks, out);
}